// round 10
// baseline (speedup 1.0000x reference)
#include <cuda_runtime.h>
#include <cstdint>

// ---------------------------------------------------------------------------
// Problem constants
// ---------------------------------------------------------------------------
#define B_DIM 8
#define L_DIM 1024
#define D_MODEL 1024
#define N_HEADS 16
#define D_KEYS 64
#define D_LLM 4096
#define HD 1024           // N_HEADS * D_KEYS
#define ML (B_DIM * L_DIM) // 8192

// Scratch (device globals: allocation-free contract)
__device__ float g_q[ML * HD];
__device__ float g_k[1024 * HD];
__device__ float g_v[1024 * HD];
__device__ float g_attn[ML * HD];

__device__ __forceinline__ uint32_t f32_to_tf32(float x) {
    uint32_t r;
    asm("cvt.rna.tf32.f32 %0, %1;" : "=r"(r) : "f"(x));
    return r;
}
__device__ __forceinline__ uint32_t smem_u32(const void* p) {
    uint32_t a;
    asm("{ .reg .u64 t; cvta.to.shared.u64 t, %1; cvt.u32.u64 %0, t; }" : "=r"(a) : "l"(p));
    return a;
}
__device__ __forceinline__ void cp_async16(uint32_t dst, const void* src, bool pred) {
    const int sz = pred ? 16 : 0;   // src-size 0 -> 16B zero-fill
    asm volatile("cp.async.cg.shared.global [%0], [%1], 16, %2;"
                 :: "r"(dst), "l"(src), "r"(sz) : "memory");
}
__device__ __forceinline__ void cp_async_commit() {
    asm volatile("cp.async.commit_group;" ::: "memory");
}
template <int N>
__device__ __forceinline__ void cp_async_wait() {
    asm volatile("cp.async.wait_group %0;" :: "n"(N) : "memory");
}

#define MMA_TF32(d, a, b0v, b1v)                                               \
    asm volatile(                                                              \
        "mma.sync.aligned.m16n8k8.row.col.f32.tf32.tf32.f32 "                  \
        "{%0,%1,%2,%3}, {%4,%5,%6,%7}, {%8,%9}, {%0,%1,%2,%3};"                \
        : "+f"((d)[0]), "+f"((d)[1]), "+f"((d)[2]), "+f"((d)[3])               \
        : "r"((a)[0]), "r"((a)[1]), "r"((a)[2]), "r"((a)[3]),                  \
          "r"(b0v), "r"(b1v))

// ---------------------------------------------------------------------------
// TF32 tensor-core GEMM, cp.async 4-stage pipeline, BK=16, single-sync loop:
//   C[M,N] = A[M,K] @ W[K,N] + bias[N]
// 128x128 CTA tile, 256 threads (8 warps, 2x4), warp tile 64x32.
// Dynamic SMEM holds raw fp32; tf32 cvt at fragment read.
// ---------------------------------------------------------------------------
#define BMT 128
#define BNT 128
#define BKT 16
#define APITCH 20     // banks (20*grp + tig + kb) mod 32 all distinct
#define BPITCH 136
#define STAGES 4
#define A_STAGE_W (BMT * APITCH)   // 2560 floats
#define B_STAGE_W (BKT * BPITCH)   // 2176 floats
#define GEMM_SMEM ((STAGES * (A_STAGE_W + B_STAGE_W)) * 4)   // 75776 B

__device__ __forceinline__
void gemm_body(const float* __restrict__ A, const float* __restrict__ W,
               const float* __restrict__ bias, float* __restrict__ C,
               int M, int N, int K, int bx, int by)
{
    extern __shared__ float dyn[];
    float* Asm = dyn;                          // [STAGES][128][APITCH]
    float* Bsm = dyn + STAGES * A_STAGE_W;     // [STAGES][16][BPITCH]

    const int tid  = threadIdx.x;
    const int lane = tid & 31;
    const int warp = tid >> 5;
    const int wm = (warp >> 2) * 64;
    const int wn = (warp & 3) * 32;
    const int grp = lane >> 2;
    const int tig = lane & 3;

    const int m0 = by * BMT;
    const int n0 = bx * BNT;

    // loaders: 2 float4 per operand per stage per thread
    const int a_row = tid >> 1;            // 0..127
    const int a_k   = (tid & 1) << 2;      // 0 or 4 (and +8)
    const int b_k   = tid >> 5;            // 0..7 (and +8)
    const int b_n   = (tid & 31) << 2;     // 0..124

    const bool a_ok = (m0 + a_row) < M;
    const float* a_src = A + (size_t)(m0 + a_row) * K + a_k;
    const float* b_src = W + (size_t)b_k * N + n0 + b_n;

    const uint32_t a_dst0 = smem_u32(Asm + a_row * APITCH + a_k);
    const uint32_t b_dst0 = smem_u32(Bsm + b_k * BPITCH + b_n);
    const uint32_t a_st = (uint32_t)(A_STAGE_W * 4);
    const uint32_t b_st = (uint32_t)(B_STAGE_W * 4);
    const uint32_t b_half = (uint32_t)(8 * BPITCH * 4);

    float acc[4][4][4];
    #pragma unroll
    for (int i = 0; i < 4; i++)
        #pragma unroll
        for (int j = 0; j < 4; j++)
            #pragma unroll
            for (int r = 0; r < 4; r++) acc[i][j][r] = 0.0f;

    const int nk = K / BKT;

    // ---- prologue: fill STAGES-1 stages ----
    #pragma unroll
    for (int s = 0; s < STAGES - 1; s++) {
        if (s < nk) {
            cp_async16(a_dst0 + s * a_st,      a_src + (size_t)s * BKT, a_ok);
            cp_async16(a_dst0 + s * a_st + 32, a_src + (size_t)s * BKT + 8, a_ok);
            cp_async16(b_dst0 + s * b_st,          b_src + (size_t)s * BKT * N, true);
            cp_async16(b_dst0 + s * b_st + b_half, b_src + (size_t)(s * BKT + 8) * N, true);
        }
        cp_async_commit();
    }

    for (int kt = 0; kt < nk; kt++) {
        const int cur = kt & (STAGES - 1);
        cp_async_wait<STAGES - 2>();
        __syncthreads();

        // issue load for stage kt+STAGES-1 (safe: post-sync, readers of the
        // target stage finished in iteration kt-1)
        {
            const int kn = kt + STAGES - 1;
            if (kn < nk) {
                const int st = kn & (STAGES - 1);
                cp_async16(a_dst0 + st * a_st,      a_src + (size_t)kn * BKT, a_ok);
                cp_async16(a_dst0 + st * a_st + 32, a_src + (size_t)kn * BKT + 8, a_ok);
                cp_async16(b_dst0 + st * b_st,          b_src + (size_t)kn * BKT * N, true);
                cp_async16(b_dst0 + st * b_st + b_half, b_src + (size_t)(kn * BKT + 8) * N, true);
            }
            cp_async_commit();
        }

        const float* Ac = Asm + cur * A_STAGE_W;
        const float* Bc = Bsm + cur * B_STAGE_W;

        #pragma unroll
        for (int kb = 0; kb < BKT; kb += 8) {
            uint32_t af[4][4], bf[4][2];
            #pragma unroll
            for (int tm = 0; tm < 4; tm++) {
                const int rb = wm + tm * 16 + grp;
                af[tm][0] = f32_to_tf32(Ac[rb * APITCH + kb + tig]);
                af[tm][1] = f32_to_tf32(Ac[(rb + 8) * APITCH + kb + tig]);
                af[tm][2] = f32_to_tf32(Ac[rb * APITCH + kb + tig + 4]);
                af[tm][3] = f32_to_tf32(Ac[(rb + 8) * APITCH + kb + tig + 4]);
            }
            #pragma unroll
            for (int tn = 0; tn < 4; tn++) {
                const int nb = wn + tn * 8 + grp;
                bf[tn][0] = f32_to_tf32(Bc[(kb + tig) * BPITCH + nb]);
                bf[tn][1] = f32_to_tf32(Bc[(kb + tig + 4) * BPITCH + nb]);
            }
            #pragma unroll
            for (int tm = 0; tm < 4; tm++)
                #pragma unroll
                for (int tn = 0; tn < 4; tn++)
                    MMA_TF32(acc[tm][tn], af[tm], bf[tn][0], bf[tn][1]);
        }
        // no bottom sync: top sync of next iter orders reads before overwrite
    }

    // ---- epilogue: bias + store ----
    #pragma unroll
    for (int tm = 0; tm < 4; tm++) {
        const int row  = m0 + wm + tm * 16 + grp;
        const int row2 = row + 8;
        #pragma unroll
        for (int tn = 0; tn < 4; tn++) {
            const int col = n0 + wn + tn * 8 + 2 * tig;
            const float b0v = bias[col];
            const float b1v = bias[col + 1];
            if (row < M) {
                float2 o = make_float2(acc[tm][tn][0] + b0v, acc[tm][tn][1] + b1v);
                *(float2*)(C + (size_t)row * N + col) = o;
            }
            if (row2 < M) {
                float2 o = make_float2(acc[tm][tn][2] + b0v, acc[tm][tn][3] + b1v);
                *(float2*)(C + (size_t)row2 * N + col) = o;
            }
        }
    }
}

__global__ __launch_bounds__(256, 2)
void gemm_tf32_kernel(const float* __restrict__ A, const float* __restrict__ W,
                      const float* __restrict__ bias, float* __restrict__ C,
                      int M, int N, int K)
{
    gemm_body(A, W, bias, C, M, N, K, blockIdx.x, blockIdx.y);
}

// Q/K/V projections in one launch. grid = (8, 80):
//   y in [0,64)  -> Q proj, m-tile y ; y in [64,72) -> K ; y in [72,80) -> V
__global__ __launch_bounds__(256, 2)
void gemm_tf32_qkv_kernel(const float* __restrict__ tgt, const float* __restrict__ Wq,
                          const float* __restrict__ bq, float* __restrict__ Cq,
                          const float* __restrict__ src, const float* __restrict__ Wk,
                          const float* __restrict__ bk, float* __restrict__ Ck,
                          const float* __restrict__ val, const float* __restrict__ Wv,
                          const float* __restrict__ bv, float* __restrict__ Cv,
                          int S)
{
    const int y = blockIdx.y;
    if (y < 64)      gemm_body(tgt, Wq, bq, Cq, ML, HD, D_MODEL, blockIdx.x, y);
    else if (y < 72) gemm_body(src, Wk, bk, Ck, S,  HD, D_LLM,   blockIdx.x, y - 64);
    else             gemm_body(val, Wv, bv, Cv, S,  HD, D_LLM,   blockIdx.x, y - 72);
}

// ---------------------------------------------------------------------------
// Tensor-core flash attention (tf32 m16n8k8), head_dim = 64.
// One block per (b, h, 128-query tile). 256 threads = 8 warps. (Proven.)
// ---------------------------------------------------------------------------
#define QT 128
#define QK_PITCH 68
#define V_PITCH  72
#define P_PITCH  72

__global__ __launch_bounds__(256, 2)
void attn_tc_kernel(const float* __restrict__ q, const float* __restrict__ k,
                    const float* __restrict__ v, float* __restrict__ o_out,
                    const float* __restrict__ alpha, const float* __restrict__ beta,
                    int S)
{
    extern __shared__ uint32_t smu[];
    uint32_t* Ks = smu;
    uint32_t* Vs = Ks + 64 * QK_PITCH;
    uint32_t* Ps = Vs + 64 * V_PITCH;

    const int tid  = threadIdx.x;
    const int lane = tid & 31;
    const int warp = tid >> 5;
    const int grp  = lane >> 2;
    const int tig  = lane & 3;

    const int l0 = blockIdx.x * QT;
    const int b  = blockIdx.y >> 4;
    const int h  = blockIdx.y & 15;

    const float scale = alpha[0] * beta[0] * 0.125f;

    const float* qbase = q + ((size_t)(b * L_DIM + l0)) * HD + h * D_KEYS;
    #pragma unroll
    for (int p = 0; p < 8; p++) {
        const int idx = p * 256 + tid;
        const int row = idx >> 4;
        const int e4  = (idx & 15) << 2;
        float4 t = *(const float4*)(qbase + (size_t)row * HD + e4);
        uint32_t* d = Ps + row * P_PITCH + e4;
        d[0] = f32_to_tf32(t.x); d[1] = f32_to_tf32(t.y);
        d[2] = f32_to_tf32(t.z); d[3] = f32_to_tf32(t.w);
    }
    __syncthreads();

    uint32_t qf[8][4];
    {
        const int qrow = warp * 16 + grp;
        #pragma unroll
        for (int ks = 0; ks < 8; ks++) {
            qf[ks][0] = Ps[qrow * P_PITCH + ks * 8 + tig];
            qf[ks][1] = Ps[(qrow + 8) * P_PITCH + ks * 8 + tig];
            qf[ks][2] = Ps[qrow * P_PITCH + ks * 8 + tig + 4];
            qf[ks][3] = Ps[(qrow + 8) * P_PITCH + ks * 8 + tig + 4];
        }
    }

    float m0r = -1e30f, m1r = -1e30f, l0r = 0.0f, l1r = 0.0f;
    float oa[8][4];
    #pragma unroll
    for (int nt = 0; nt < 8; nt++)
        #pragma unroll
        for (int r = 0; r < 4; r++) oa[nt][r] = 0.0f;

    const int nTiles = (S + 63) >> 6;
    for (int ts = 0; ts < nTiles; ts++) {
        const int s0 = ts * 64;
        __syncthreads();

        const float* kb2 = k + (size_t)s0 * HD + h * D_KEYS;
        const float* vb2 = v + (size_t)s0 * HD + h * D_KEYS;
        #pragma unroll
        for (int p = 0; p < 4; p++) {
            const int idx = p * 256 + tid;
            const int j  = idx >> 4;
            const int e4 = (idx & 15) << 2;
            float4 tk, tv;
            if (s0 + j < S) {
                tk = *(const float4*)(kb2 + (size_t)j * HD + e4);
                tv = *(const float4*)(vb2 + (size_t)j * HD + e4);
            } else {
                tk = make_float4(0.f, 0.f, 0.f, 0.f);
                tv = tk;
            }
            uint32_t* dk = Ks + j * QK_PITCH + e4;
            dk[0] = f32_to_tf32(tk.x); dk[1] = f32_to_tf32(tk.y);
            dk[2] = f32_to_tf32(tk.z); dk[3] = f32_to_tf32(tk.w);
            uint32_t* dv = Vs + j * V_PITCH + e4;
            dv[0] = f32_to_tf32(tv.x); dv[1] = f32_to_tf32(tv.y);
            dv[2] = f32_to_tf32(tv.z); dv[3] = f32_to_tf32(tv.w);
        }
        __syncthreads();

        float sc[8][4];
        #pragma unroll
        for (int nt = 0; nt < 8; nt++)
            #pragma unroll
            for (int r = 0; r < 4; r++) sc[nt][r] = 0.0f;

        #pragma unroll
        for (int ks = 0; ks < 8; ks++) {
            #pragma unroll
            for (int nt = 0; nt < 8; nt++) {
                const uint32_t b0v = Ks[(nt * 8 + grp) * QK_PITCH + ks * 8 + tig];
                const uint32_t b1v = Ks[(nt * 8 + grp) * QK_PITCH + ks * 8 + tig + 4];
                MMA_TF32(sc[nt], qf[ks], b0v, b1v);
            }
        }

        #pragma unroll
        for (int nt = 0; nt < 8; nt++) {
            const int c0 = s0 + nt * 8 + 2 * tig;
            const bool v0 = c0 < S, v1 = (c0 + 1) < S;
            sc[nt][0] = v0 ? sc[nt][0] * scale : -1e30f;
            sc[nt][1] = v1 ? sc[nt][1] * scale : -1e30f;
            sc[nt][2] = v0 ? sc[nt][2] * scale : -1e30f;
            sc[nt][3] = v1 ? sc[nt][3] * scale : -1e30f;
        }

        float mt0 = -1e30f, mt1 = -1e30f;
        #pragma unroll
        for (int nt = 0; nt < 8; nt++) {
            mt0 = fmaxf(mt0, fmaxf(sc[nt][0], sc[nt][1]));
            mt1 = fmaxf(mt1, fmaxf(sc[nt][2], sc[nt][3]));
        }
        mt0 = fmaxf(mt0, __shfl_xor_sync(0xffffffffu, mt0, 1));
        mt0 = fmaxf(mt0, __shfl_xor_sync(0xffffffffu, mt0, 2));
        mt1 = fmaxf(mt1, __shfl_xor_sync(0xffffffffu, mt1, 1));
        mt1 = fmaxf(mt1, __shfl_xor_sync(0xffffffffu, mt1, 2));

        const float mn0 = fmaxf(m0r, mt0);
        const float mn1 = fmaxf(m1r, mt1);
        const float fac0 = __expf(m0r - mn0);
        const float fac1 = __expf(m1r - mn1);
        m0r = mn0; m1r = mn1;
        l0r *= fac0; l1r *= fac1;
        #pragma unroll
        for (int nt = 0; nt < 8; nt++) {
            oa[nt][0] *= fac0; oa[nt][1] *= fac0;
            oa[nt][2] *= fac1; oa[nt][3] *= fac1;
        }

        float rs0 = 0.0f, rs1 = 0.0f;
        #pragma unroll
        for (int nt = 0; nt < 8; nt++) {
            sc[nt][0] = __expf(sc[nt][0] - mn0);
            sc[nt][1] = __expf(sc[nt][1] - mn0);
            sc[nt][2] = __expf(sc[nt][2] - mn1);
            sc[nt][3] = __expf(sc[nt][3] - mn1);
            rs0 += sc[nt][0] + sc[nt][1];
            rs1 += sc[nt][2] + sc[nt][3];
        }
        rs0 += __shfl_xor_sync(0xffffffffu, rs0, 1);
        rs0 += __shfl_xor_sync(0xffffffffu, rs0, 2);
        rs1 += __shfl_xor_sync(0xffffffffu, rs1, 1);
        rs1 += __shfl_xor_sync(0xffffffffu, rs1, 2);
        l0r += rs0; l1r += rs1;

        {
            const int pr0 = warp * 16 + grp;
            #pragma unroll
            for (int nt = 0; nt < 8; nt++) {
                uint2 p01 = make_uint2(f32_to_tf32(sc[nt][0]), f32_to_tf32(sc[nt][1]));
                uint2 p23 = make_uint2(f32_to_tf32(sc[nt][2]), f32_to_tf32(sc[nt][3]));
                *(uint2*)&Ps[pr0 * P_PITCH + nt * 8 + 2 * tig] = p01;
                *(uint2*)&Ps[(pr0 + 8) * P_PITCH + nt * 8 + 2 * tig] = p23;
            }
        }
        __syncwarp();

        #pragma unroll
        for (int ks = 0; ks < 8; ks++) {
            uint32_t af[4];
            const int pr0 = warp * 16 + grp;
            af[0] = Ps[pr0 * P_PITCH + ks * 8 + tig];
            af[1] = Ps[(pr0 + 8) * P_PITCH + ks * 8 + tig];
            af[2] = Ps[pr0 * P_PITCH + ks * 8 + tig + 4];
            af[3] = Ps[(pr0 + 8) * P_PITCH + ks * 8 + tig + 4];
            #pragma unroll
            for (int nt = 0; nt < 8; nt++) {
                const uint32_t b0v = Vs[(ks * 8 + tig) * V_PITCH + nt * 8 + grp];
                const uint32_t b1v = Vs[(ks * 8 + tig + 4) * V_PITCH + nt * 8 + grp];
                MMA_TF32(oa[nt], af, b0v, b1v);
            }
        }
    }

    const float inv0 = 1.0f / l0r;
    const float inv1 = 1.0f / l1r;
    float* ob = o_out + ((size_t)(b * L_DIM + l0 + warp * 16 + grp)) * HD + h * D_KEYS;
    #pragma unroll
    for (int nt = 0; nt < 8; nt++) {
        const int col = nt * 8 + 2 * tig;
        *(float2*)(ob + col) = make_float2(oa[nt][0] * inv0, oa[nt][1] * inv0);
        *(float2*)(ob + (size_t)8 * HD + col) = make_float2(oa[nt][2] * inv1, oa[nt][3] * inv1);
    }
}

// ---------------------------------------------------------------------------
// Launch
// ---------------------------------------------------------------------------
extern "C" void kernel_launch(void* const* d_in, const int* in_sizes, int n_in,
                              void* d_out, int out_size)
{
    const float* target = (const float*)d_in[0];
    const float* source = (const float*)d_in[1];
    const float* value  = (const float*)d_in[2];
    const float* Wq = (const float*)d_in[3];
    const float* bq = (const float*)d_in[4];
    const float* Wk = (const float*)d_in[5];
    const float* bk = (const float*)d_in[6];
    const float* Wv = (const float*)d_in[7];
    const float* bv = (const float*)d_in[8];
    const float* Wo = (const float*)d_in[9];
    const float* bo = (const float*)d_in[10];
    const float* alpha = (const float*)d_in[11];
    const float* beta  = (const float*)d_in[12];
    float* out = (float*)d_out;

    const int S = in_sizes[1] / D_LLM;   // 1000

    float *qb, *kb, *vb, *ab;
    cudaGetSymbolAddress((void**)&qb, g_q);
    cudaGetSymbolAddress((void**)&kb, g_k);
    cudaGetSymbolAddress((void**)&vb, g_v);
    cudaGetSymbolAddress((void**)&ab, g_attn);

    cudaFuncSetAttribute(gemm_tf32_kernel,
                         cudaFuncAttributeMaxDynamicSharedMemorySize, GEMM_SMEM);
    cudaFuncSetAttribute(gemm_tf32_qkv_kernel,
                         cudaFuncAttributeMaxDynamicSharedMemorySize, GEMM_SMEM);

    dim3 blk(256);

    // Q, K, V projections in one launch
    gemm_tf32_qkv_kernel<<<dim3(HD / BNT, 80), blk, GEMM_SMEM>>>(
        target, Wq, bq, qb, source, Wk, bk, kb, value, Wv, bv, vb, S);

    // fused tensor-core attention
    const size_t asmem = (64 * QK_PITCH + 64 * V_PITCH + QT * P_PITCH) * sizeof(uint32_t);
    cudaFuncSetAttribute(attn_tc_kernel, cudaFuncAttributeMaxDynamicSharedMemorySize, (int)asmem);
    attn_tc_kernel<<<dim3(L_DIM / QT, B_DIM * N_HEADS), blk, asmem>>>(
        qb, kb, vb, ab, alpha, beta, S);

    // out = attn @ Wo + bo
    gemm_tf32_kernel<<<dim3(D_LLM / BNT, ML / BMT), blk, GEMM_SMEM>>>(
        ab, Wo, bo, out, ML, D_LLM, D_MODEL);
}

// round 11
// speedup vs baseline: 1.1150x; 1.1150x over previous
#include <cuda_runtime.h>
#include <cstdint>

// ---------------------------------------------------------------------------
// Problem constants
// ---------------------------------------------------------------------------
#define B_DIM 8
#define L_DIM 1024
#define D_MODEL 1024
#define N_HEADS 16
#define D_KEYS 64
#define D_LLM 4096
#define HD 1024           // N_HEADS * D_KEYS
#define ML (B_DIM * L_DIM) // 8192

// Scratch (device globals: allocation-free contract)
__device__ float g_q[ML * HD];
__device__ float g_k[1024 * HD];
__device__ float g_v[1024 * HD];
__device__ float g_attn[ML * HD];

__device__ __forceinline__ uint32_t f32_to_tf32(float x) {
    uint32_t r;
    asm("cvt.rna.tf32.f32 %0, %1;" : "=r"(r) : "f"(x));
    return r;
}
__device__ __forceinline__ uint32_t smem_u32(const void* p) {
    uint32_t a;
    asm("{ .reg .u64 t; cvta.to.shared.u64 t, %1; cvt.u32.u64 %0, t; }" : "=r"(a) : "l"(p));
    return a;
}
__device__ __forceinline__ void cp_async16(uint32_t dst, const void* src, bool pred) {
    const int sz = pred ? 16 : 0;   // src-size 0 -> 16B zero-fill
    asm volatile("cp.async.cg.shared.global [%0], [%1], 16, %2;"
                 :: "r"(dst), "l"(src), "r"(sz) : "memory");
}
__device__ __forceinline__ void cp_async_commit() {
    asm volatile("cp.async.commit_group;" ::: "memory");
}
template <int N>
__device__ __forceinline__ void cp_async_wait() {
    asm volatile("cp.async.wait_group %0;" :: "n"(N) : "memory");
}

#define MMA_TF32(d, a, b0v, b1v)                                               \
    asm volatile(                                                              \
        "mma.sync.aligned.m16n8k8.row.col.f32.tf32.tf32.f32 "                  \
        "{%0,%1,%2,%3}, {%4,%5,%6,%7}, {%8,%9}, {%0,%1,%2,%3};"                \
        : "+f"((d)[0]), "+f"((d)[1]), "+f"((d)[2]), "+f"((d)[3])               \
        : "r"((a)[0]), "r"((a)[1]), "r"((a)[2]), "r"((a)[3]),                  \
          "r"(b0v), "r"(b1v))

// ---------------------------------------------------------------------------
// TF32 tensor-core GEMM, cp.async 4-stage pipeline (round-9 proven config):
//   C[M,N] = A[M,K] @ W[K,N] + bias[N]
// 128x128 CTA tile, BK=8, 256 threads (8 warps, 2x4), warp tile 64x32.
// SMEM holds raw fp32; tf32 cvt at fragment read. ONE sync per k-iter.
// ---------------------------------------------------------------------------
#define BMT 128
#define BNT 128
#define BKT 8
#define APITCH 12
#define BPITCH 136
#define STAGES 4

__device__ __forceinline__
void gemm_body(const float* __restrict__ A, const float* __restrict__ W,
               const float* __restrict__ bias, float* __restrict__ C,
               int M, int N, int K)
{
    __shared__ float As[STAGES][BMT][APITCH];   // 24 KB
    __shared__ float Bs[STAGES][BKT][BPITCH];   // 17 KB

    const int tid  = threadIdx.x;
    const int lane = tid & 31;
    const int warp = tid >> 5;
    const int wm = (warp >> 2) * 64;
    const int wn = (warp & 3) * 32;
    const int grp = lane >> 2;
    const int tig = lane & 3;

    const int m0 = blockIdx.y * BMT;
    const int n0 = blockIdx.x * BNT;

    const int a_row = tid >> 1;            // 0..127
    const int a_k   = (tid & 1) << 2;      // 0 or 4
    const int b_k   = tid >> 5;            // 0..7
    const int b_n   = (tid & 31) << 2;     // 0..124

    const bool a_ok = (m0 + a_row) < M;
    const float* a_src = A + (size_t)(m0 + a_row) * K + a_k;
    const float* b_src = W + (size_t)b_k * N + n0 + b_n;

    const uint32_t a_dst0 = smem_u32(&As[0][a_row][a_k]);
    const uint32_t b_dst0 = smem_u32(&Bs[0][b_k][b_n]);
    const uint32_t a_stride = (uint32_t)(BMT * APITCH * 4);
    const uint32_t b_stride = (uint32_t)(BKT * BPITCH * 4);

    float acc[4][4][4];
    #pragma unroll
    for (int i = 0; i < 4; i++)
        #pragma unroll
        for (int j = 0; j < 4; j++)
            #pragma unroll
            for (int r = 0; r < 4; r++) acc[i][j][r] = 0.0f;

    const int nk = K / BKT;

    // ---- prologue: fill STAGES-1 stages ----
    #pragma unroll
    for (int s = 0; s < STAGES - 1; s++) {
        if (s < nk) {
            cp_async16(a_dst0 + s * a_stride, a_src + (size_t)s * BKT, a_ok);
            cp_async16(b_dst0 + s * b_stride, b_src + (size_t)s * BKT * N, true);
        }
        cp_async_commit();
    }

    for (int kt = 0; kt < nk; kt++) {
        const int cur = kt & (STAGES - 1);
        cp_async_wait<STAGES - 2>();
        __syncthreads();
        // Single barrier per iteration. Safe: the copy issued below targets
        // stage kt+3 == kt-1 (mod 4), whose readers all finished in iter kt-1;
        // this barrier orders those reads before the new copy is issued.

        {
            const int kn = kt + STAGES - 1;
            if (kn < nk) {
                const int st = kn & (STAGES - 1);
                cp_async16(a_dst0 + st * a_stride, a_src + (size_t)kn * BKT, a_ok);
                cp_async16(b_dst0 + st * b_stride, b_src + (size_t)kn * BKT * N, true);
            }
            cp_async_commit();
        }

        // fragments (fp32 -> tf32 at read)
        uint32_t af[4][4], bf[4][2];
        #pragma unroll
        for (int tm = 0; tm < 4; tm++) {
            const int rb = wm + tm * 16 + grp;
            af[tm][0] = f32_to_tf32(As[cur][rb][tig]);
            af[tm][1] = f32_to_tf32(As[cur][rb + 8][tig]);
            af[tm][2] = f32_to_tf32(As[cur][rb][tig + 4]);
            af[tm][3] = f32_to_tf32(As[cur][rb + 8][tig + 4]);
        }
        #pragma unroll
        for (int tn = 0; tn < 4; tn++) {
            const int nb = wn + tn * 8 + grp;
            bf[tn][0] = f32_to_tf32(Bs[cur][tig][nb]);
            bf[tn][1] = f32_to_tf32(Bs[cur][tig + 4][nb]);
        }

        #pragma unroll
        for (int tm = 0; tm < 4; tm++)
            #pragma unroll
            for (int tn = 0; tn < 4; tn++)
                MMA_TF32(acc[tm][tn], af[tm], bf[tn][0], bf[tn][1]);
        // no bottom sync
    }

    // ---- epilogue: bias + store ----
    #pragma unroll
    for (int tm = 0; tm < 4; tm++) {
        const int row  = m0 + wm + tm * 16 + grp;
        const int row2 = row + 8;
        #pragma unroll
        for (int tn = 0; tn < 4; tn++) {
            const int col = n0 + wn + tn * 8 + 2 * tig;
            const float b0v = bias[col];
            const float b1v = bias[col + 1];
            if (row < M) {
                float2 o = make_float2(acc[tm][tn][0] + b0v, acc[tm][tn][1] + b1v);
                *(float2*)(C + (size_t)row * N + col) = o;
            }
            if (row2 < M) {
                float2 o = make_float2(acc[tm][tn][2] + b0v, acc[tm][tn][3] + b1v);
                *(float2*)(C + (size_t)row2 * N + col) = o;
            }
        }
    }
}

__global__ __launch_bounds__(256, 2)
void gemm_tf32_kernel(const float* __restrict__ A, const float* __restrict__ W,
                      const float* __restrict__ bias, float* __restrict__ C,
                      int M, int N, int K)
{
    gemm_body(A, W, bias, C, M, N, K);
}

__global__ __launch_bounds__(256, 2)
void gemm_tf32_dual_kernel(const float* __restrict__ A0, const float* __restrict__ W0,
                           const float* __restrict__ b0, float* __restrict__ C0,
                           const float* __restrict__ A1, const float* __restrict__ W1,
                           const float* __restrict__ b1, float* __restrict__ C1,
                           int M, int N, int K)
{
    if (blockIdx.z == 0) gemm_body(A0, W0, b0, C0, M, N, K);
    else                 gemm_body(A1, W1, b1, C1, M, N, K);
}

// ---------------------------------------------------------------------------
// Tensor-core flash attention (tf32 m16n8k8), head_dim = 64.
// One block per (b, h, 128-query tile). 256 threads = 8 warps. (Proven.)
// ---------------------------------------------------------------------------
#define QT 128
#define QK_PITCH 68
#define V_PITCH  72
#define P_PITCH  72

__global__ __launch_bounds__(256, 2)
void attn_tc_kernel(const float* __restrict__ q, const float* __restrict__ k,
                    const float* __restrict__ v, float* __restrict__ o_out,
                    const float* __restrict__ alpha, const float* __restrict__ beta,
                    int S)
{
    extern __shared__ uint32_t smu[];
    uint32_t* Ks = smu;
    uint32_t* Vs = Ks + 64 * QK_PITCH;
    uint32_t* Ps = Vs + 64 * V_PITCH;

    const int tid  = threadIdx.x;
    const int lane = tid & 31;
    const int warp = tid >> 5;
    const int grp  = lane >> 2;
    const int tig  = lane & 3;

    const int l0 = blockIdx.x * QT;
    const int b  = blockIdx.y >> 4;
    const int h  = blockIdx.y & 15;

    const float scale = alpha[0] * beta[0] * 0.125f;

    const float* qbase = q + ((size_t)(b * L_DIM + l0)) * HD + h * D_KEYS;
    #pragma unroll
    for (int p = 0; p < 8; p++) {
        const int idx = p * 256 + tid;
        const int row = idx >> 4;
        const int e4  = (idx & 15) << 2;
        float4 t = *(const float4*)(qbase + (size_t)row * HD + e4);
        uint32_t* d = Ps + row * P_PITCH + e4;
        d[0] = f32_to_tf32(t.x); d[1] = f32_to_tf32(t.y);
        d[2] = f32_to_tf32(t.z); d[3] = f32_to_tf32(t.w);
    }
    __syncthreads();

    uint32_t qf[8][4];
    {
        const int qrow = warp * 16 + grp;
        #pragma unroll
        for (int ks = 0; ks < 8; ks++) {
            qf[ks][0] = Ps[qrow * P_PITCH + ks * 8 + tig];
            qf[ks][1] = Ps[(qrow + 8) * P_PITCH + ks * 8 + tig];
            qf[ks][2] = Ps[qrow * P_PITCH + ks * 8 + tig + 4];
            qf[ks][3] = Ps[(qrow + 8) * P_PITCH + ks * 8 + tig + 4];
        }
    }

    float m0r = -1e30f, m1r = -1e30f, l0r = 0.0f, l1r = 0.0f;
    float oa[8][4];
    #pragma unroll
    for (int nt = 0; nt < 8; nt++)
        #pragma unroll
        for (int r = 0; r < 4; r++) oa[nt][r] = 0.0f;

    const int nTiles = (S + 63) >> 6;
    for (int ts = 0; ts < nTiles; ts++) {
        const int s0 = ts * 64;
        __syncthreads();

        const float* kb2 = k + (size_t)s0 * HD + h * D_KEYS;
        const float* vb2 = v + (size_t)s0 * HD + h * D_KEYS;
        #pragma unroll
        for (int p = 0; p < 4; p++) {
            const int idx = p * 256 + tid;
            const int j  = idx >> 4;
            const int e4 = (idx & 15) << 2;
            float4 tk, tv;
            if (s0 + j < S) {
                tk = *(const float4*)(kb2 + (size_t)j * HD + e4);
                tv = *(const float4*)(vb2 + (size_t)j * HD + e4);
            } else {
                tk = make_float4(0.f, 0.f, 0.f, 0.f);
                tv = tk;
            }
            uint32_t* dk = Ks + j * QK_PITCH + e4;
            dk[0] = f32_to_tf32(tk.x); dk[1] = f32_to_tf32(tk.y);
            dk[2] = f32_to_tf32(tk.z); dk[3] = f32_to_tf32(tk.w);
            uint32_t* dv = Vs + j * V_PITCH + e4;
            dv[0] = f32_to_tf32(tv.x); dv[1] = f32_to_tf32(tv.y);
            dv[2] = f32_to_tf32(tv.z); dv[3] = f32_to_tf32(tv.w);
        }
        __syncthreads();

        float sc[8][4];
        #pragma unroll
        for (int nt = 0; nt < 8; nt++)
            #pragma unroll
            for (int r = 0; r < 4; r++) sc[nt][r] = 0.0f;

        #pragma unroll
        for (int ks = 0; ks < 8; ks++) {
            #pragma unroll
            for (int nt = 0; nt < 8; nt++) {
                const uint32_t b0v = Ks[(nt * 8 + grp) * QK_PITCH + ks * 8 + tig];
                const uint32_t b1v = Ks[(nt * 8 + grp) * QK_PITCH + ks * 8 + tig + 4];
                MMA_TF32(sc[nt], qf[ks], b0v, b1v);
            }
        }

        #pragma unroll
        for (int nt = 0; nt < 8; nt++) {
            const int c0 = s0 + nt * 8 + 2 * tig;
            const bool v0 = c0 < S, v1 = (c0 + 1) < S;
            sc[nt][0] = v0 ? sc[nt][0] * scale : -1e30f;
            sc[nt][1] = v1 ? sc[nt][1] * scale : -1e30f;
            sc[nt][2] = v0 ? sc[nt][2] * scale : -1e30f;
            sc[nt][3] = v1 ? sc[nt][3] * scale : -1e30f;
        }

        float mt0 = -1e30f, mt1 = -1e30f;
        #pragma unroll
        for (int nt = 0; nt < 8; nt++) {
            mt0 = fmaxf(mt0, fmaxf(sc[nt][0], sc[nt][1]));
            mt1 = fmaxf(mt1, fmaxf(sc[nt][2], sc[nt][3]));
        }
        mt0 = fmaxf(mt0, __shfl_xor_sync(0xffffffffu, mt0, 1));
        mt0 = fmaxf(mt0, __shfl_xor_sync(0xffffffffu, mt0, 2));
        mt1 = fmaxf(mt1, __shfl_xor_sync(0xffffffffu, mt1, 1));
        mt1 = fmaxf(mt1, __shfl_xor_sync(0xffffffffu, mt1, 2));

        const float mn0 = fmaxf(m0r, mt0);
        const float mn1 = fmaxf(m1r, mt1);
        const float fac0 = __expf(m0r - mn0);
        const float fac1 = __expf(m1r - mn1);
        m0r = mn0; m1r = mn1;
        l0r *= fac0; l1r *= fac1;
        #pragma unroll
        for (int nt = 0; nt < 8; nt++) {
            oa[nt][0] *= fac0; oa[nt][1] *= fac0;
            oa[nt][2] *= fac1; oa[nt][3] *= fac1;
        }

        float rs0 = 0.0f, rs1 = 0.0f;
        #pragma unroll
        for (int nt = 0; nt < 8; nt++) {
            sc[nt][0] = __expf(sc[nt][0] - mn0);
            sc[nt][1] = __expf(sc[nt][1] - mn0);
            sc[nt][2] = __expf(sc[nt][2] - mn1);
            sc[nt][3] = __expf(sc[nt][3] - mn1);
            rs0 += sc[nt][0] + sc[nt][1];
            rs1 += sc[nt][2] + sc[nt][3];
        }
        rs0 += __shfl_xor_sync(0xffffffffu, rs0, 1);
        rs0 += __shfl_xor_sync(0xffffffffu, rs0, 2);
        rs1 += __shfl_xor_sync(0xffffffffu, rs1, 1);
        rs1 += __shfl_xor_sync(0xffffffffu, rs1, 2);
        l0r += rs0; l1r += rs1;

        {
            const int pr0 = warp * 16 + grp;
            #pragma unroll
            for (int nt = 0; nt < 8; nt++) {
                uint2 p01 = make_uint2(f32_to_tf32(sc[nt][0]), f32_to_tf32(sc[nt][1]));
                uint2 p23 = make_uint2(f32_to_tf32(sc[nt][2]), f32_to_tf32(sc[nt][3]));
                *(uint2*)&Ps[pr0 * P_PITCH + nt * 8 + 2 * tig] = p01;
                *(uint2*)&Ps[(pr0 + 8) * P_PITCH + nt * 8 + 2 * tig] = p23;
            }
        }
        __syncwarp();

        #pragma unroll
        for (int ks = 0; ks < 8; ks++) {
            uint32_t af[4];
            const int pr0 = warp * 16 + grp;
            af[0] = Ps[pr0 * P_PITCH + ks * 8 + tig];
            af[1] = Ps[(pr0 + 8) * P_PITCH + ks * 8 + tig];
            af[2] = Ps[pr0 * P_PITCH + ks * 8 + tig + 4];
            af[3] = Ps[(pr0 + 8) * P_PITCH + ks * 8 + tig + 4];
            #pragma unroll
            for (int nt = 0; nt < 8; nt++) {
                const uint32_t b0v = Vs[(ks * 8 + tig) * V_PITCH + nt * 8 + grp];
                const uint32_t b1v = Vs[(ks * 8 + tig + 4) * V_PITCH + nt * 8 + grp];
                MMA_TF32(oa[nt], af, b0v, b1v);
            }
        }
    }

    const float inv0 = 1.0f / l0r;
    const float inv1 = 1.0f / l1r;
    float* ob = o_out + ((size_t)(b * L_DIM + l0 + warp * 16 + grp)) * HD + h * D_KEYS;
    #pragma unroll
    for (int nt = 0; nt < 8; nt++) {
        const int col = nt * 8 + 2 * tig;
        *(float2*)(ob + col) = make_float2(oa[nt][0] * inv0, oa[nt][1] * inv0);
        *(float2*)(ob + (size_t)8 * HD + col) = make_float2(oa[nt][2] * inv1, oa[nt][3] * inv1);
    }
}

// ---------------------------------------------------------------------------
// Launch
// ---------------------------------------------------------------------------
extern "C" void kernel_launch(void* const* d_in, const int* in_sizes, int n_in,
                              void* d_out, int out_size)
{
    const float* target = (const float*)d_in[0];
    const float* source = (const float*)d_in[1];
    const float* value  = (const float*)d_in[2];
    const float* Wq = (const float*)d_in[3];
    const float* bq = (const float*)d_in[4];
    const float* Wk = (const float*)d_in[5];
    const float* bk = (const float*)d_in[6];
    const float* Wv = (const float*)d_in[7];
    const float* bv = (const float*)d_in[8];
    const float* Wo = (const float*)d_in[9];
    const float* bo = (const float*)d_in[10];
    const float* alpha = (const float*)d_in[11];
    const float* beta  = (const float*)d_in[12];
    float* out = (float*)d_out;

    const int S = in_sizes[1] / D_LLM;   // 1000

    float *qb, *kb, *vb, *ab;
    cudaGetSymbolAddress((void**)&qb, g_q);
    cudaGetSymbolAddress((void**)&kb, g_k);
    cudaGetSymbolAddress((void**)&vb, g_v);
    cudaGetSymbolAddress((void**)&ab, g_attn);

    dim3 blk(256);

    // Q = target @ Wq + bq
    gemm_tf32_kernel<<<dim3(HD / BNT, ML / BMT), blk>>>(target, Wq, bq, qb, ML, HD, D_MODEL);
    // K,V projections fused (2x CTA parallelism)
    gemm_tf32_dual_kernel<<<dim3(HD / BNT, (1000 + BMT - 1) / BMT, 2), blk>>>(
        source, Wk, bk, kb, value, Wv, bv, vb, S, HD, D_LLM);

    // fused tensor-core attention
    const size_t asmem = (64 * QK_PITCH + 64 * V_PITCH + QT * P_PITCH) * sizeof(uint32_t);
    cudaFuncSetAttribute(attn_tc_kernel, cudaFuncAttributeMaxDynamicSharedMemorySize, (int)asmem);
    attn_tc_kernel<<<dim3(L_DIM / QT, B_DIM * N_HEADS), blk, asmem>>>(
        qb, kb, vb, ab, alpha, beta, S);

    // out = attn @ Wo + bo
    gemm_tf32_kernel<<<dim3(D_LLM / BNT, ML / BMT), blk>>>(ab, Wo, bo, out, ML, D_LLM, D_MODEL);
}